// round 4
// baseline (speedup 1.0000x reference)
#include <cuda_runtime.h>
#include <cuda_bf16.h>
#include <math.h>

// Problem dims
#define B_   128
#define T_   512
#define E_   256
#define H_   512
#define G3   1536   // 3H (one direction's gate rows)
#define GT   3072   // both directions stacked

#define NCTA_REC    128
#define REC_THREADS 256

// ---------------- scratch (device globals; no allocation allowed) ----------------
// xpT[t][g][b]  : input projections for both dirs, b innermost  (805 MB)
__device__ float g_xpT[(size_t)T_ * GT * B_];
// g_h[dir][j][b] : hidden state, updated in place each step (512 KB)
__device__ float g_h[2 * H_ * B_];
// g_P[g][kc][b]  : per-k-chunk partial sums of h @ W_hh^T (6.3 MB, L2-resident)
__device__ float g_P[(size_t)GT * 4 * B_];
// software grid barrier state
__device__ unsigned g_barcnt;
__device__ unsigned g_bargen;

// =================================================================================
// Phase 1: input projection GEMM (gathered A).
// For a fixed t:  xpT[t][g][b] = sum_k W_ih[g][k] * emb[tok(b,t)][k] + b_ih[g]
// Grid: (T_, GT/128) ; block 256 ; CTA tile 128 g x 128 b ; microtile 8x8.
// =================================================================================
__global__ void __launch_bounds__(256) proj_kernel(
    const int* __restrict__ inputs, const float* __restrict__ emb,
    const float* __restrict__ Wf, const float* __restrict__ Wb,
    const float* __restrict__ bf, const float* __restrict__ bb)
{
    __shared__ float As[16][128];   // As[k][g]
    __shared__ float Bs[16][128];   // Bs[k][b]
    __shared__ int   toks[128];

    const int t   = blockIdx.x;
    const int g0  = blockIdx.y * 128;
    const int tid = threadIdx.x;

    if (tid < 128) toks[tid] = inputs[tid * T_ + t];
    __syncthreads();

    const int    isB  = (g0 >= G3);
    const float* W    = isB ? Wb : Wf;
    const float* bias = isB ? bb : bf;
    const int    gl0  = g0 - (isB ? G3 : 0);

    const int tx = tid & 15;   // -> 8 b's
    const int ty = tid >> 4;   // -> 8 g's

    float acc[8][8];
    #pragma unroll
    for (int i = 0; i < 8; i++)
        #pragma unroll
        for (int j = 0; j < 8; j++) acc[i][j] = 0.f;

    for (int k0 = 0; k0 < E_; k0 += 16) {
        // Load W tile (128 g x 16 k), store transposed [k][g].
        #pragma unroll
        for (int l = 0; l < 2; l++) {
            int idx = tid * 2 + l;           // 0..511
            int row = idx >> 2, q = idx & 3; // row: g-row, q: k-quad
            float4 v = *reinterpret_cast<const float4*>(
                &W[(size_t)(gl0 + row) * E_ + k0 + q * 4]);
            As[q*4+0][row] = v.x; As[q*4+1][row] = v.y;
            As[q*4+2][row] = v.z; As[q*4+3][row] = v.w;
        }
        // Load gathered emb tile (128 b x 16 k), store transposed [k][b].
        #pragma unroll
        for (int l = 0; l < 2; l++) {
            int idx = tid * 2 + l;
            int b = idx >> 2, q = idx & 3;
            float4 v = *reinterpret_cast<const float4*>(
                &emb[(size_t)toks[b] * E_ + k0 + q * 4]);
            Bs[q*4+0][b] = v.x; Bs[q*4+1][b] = v.y;
            Bs[q*4+2][b] = v.z; Bs[q*4+3][b] = v.w;
        }
        __syncthreads();

        #pragma unroll
        for (int k = 0; k < 16; k++) {
            float af[8], bfr[8];
            #pragma unroll
            for (int i = 0; i < 8; i++) af[i]  = As[k][ty*8 + i];
            #pragma unroll
            for (int i = 0; i < 8; i++) bfr[i] = Bs[k][tx*8 + i];
            #pragma unroll
            for (int i = 0; i < 8; i++)
                #pragma unroll
                for (int j = 0; j < 8; j++)
                    acc[i][j] = fmaf(af[i], bfr[j], acc[i][j]);
        }
        __syncthreads();
    }

    // Epilogue: add b_ih, write xpT[t][g][b] (b innermost -> coalesced).
    #pragma unroll
    for (int i = 0; i < 8; i++) {
        int g = g0 + ty*8 + i;
        float bv = bias[gl0 + ty*8 + i];
        float* dst = &g_xpT[((size_t)t * GT + g) * B_ + tx*8];
        float4 v0 = make_float4(acc[i][0]+bv, acc[i][1]+bv, acc[i][2]+bv, acc[i][3]+bv);
        float4 v1 = make_float4(acc[i][4]+bv, acc[i][5]+bv, acc[i][6]+bv, acc[i][7]+bv);
        *reinterpret_cast<float4*>(dst)     = v0;
        *reinterpret_cast<float4*>(dst + 4) = v1;
    }
}

// =================================================================================
// Software grid barrier (all NCTA_REC CTAs are co-resident: 1 CTA/SM, 128 <= 148).
// =================================================================================
__device__ __forceinline__ void grid_barrier() {
    __syncthreads();
    if (threadIdx.x == 0) {
        volatile unsigned* genp = &g_bargen;
        unsigned old = *genp;
        __threadfence();
        if (atomicAdd(&g_barcnt, 1u) == NCTA_REC - 1) {
            atomicExch(&g_barcnt, 0u);
            __threadfence();
            *genp = old + 1;
        } else {
            while (*genp == old) { __nanosleep(32); }
        }
    }
    __syncthreads();
}

// =================================================================================
// Phase 2: persistent recurrence kernel.
//   128 CTAs = 32 gate-tiles (96 gate rows) x 4 k-chunks (128 k each).
//   W_hh chunk (96x128 f32 = 48KB) resident in SMEM across all 512 steps.
//   Per step:
//     A) partial[g][kc][b] = sum_{k in chunk} h[dir][k][b] * W_hh[g][k]   -> g_P
//     B) gating: reduce 4 partials + b_hh + xp, apply GRU cell, update g_h in place
// =================================================================================
__global__ void __launch_bounds__(REC_THREADS, 1) rec_kernel(
    const float* __restrict__ Whf, const float* __restrict__ Whb,
    const float* __restrict__ bhf, const float* __restrict__ bhb)
{
    extern __shared__ float sm[];
    float* ws = sm;              // [128 k][96 g]   48 KB
    float* hs = sm + 128*96;     // [128 k][128 b]  64 KB

    const int cta   = blockIdx.x;
    const int tid   = threadIdx.x;
    const int gtile = cta >> 2;
    const int kc    = cta & 3;
    const int gg0   = gtile * 96;             // global gate-row base (0..3071)
    const int dir   = (gg0 >= G3) ? 1 : 0;
    const int gl0   = gg0 - dir * G3;         // local gate row within W_hh
    const float* Wh = dir ? Whb : Whf;

    // Load W_hh chunk to SMEM, transposed to [k][g]. (one-time)
    for (int i = tid; i < 96*128; i += REC_THREADS) {
        int r = i >> 7, k = i & 127;
        ws[k*96 + r] = Wh[(size_t)(gl0 + r) * H_ + kc*128 + k];
    }
    // Zero hidden state (each CTA zeroes its 1024-float slice of 131072).
    for (int i = cta*1024 + tid; i < cta*1024 + 1024; i += REC_THREADS)
        g_h[i] = 0.f;
    __threadfence();
    grid_barrier();

    const int tx  = tid & 15;          // -> 8 b's
    const int ty  = tid >> 4;          // -> 6 g's
    const int b0  = tx * 8;
    const int wg0 = ty * 6;
    const int pb_b  = tid & 127;       // phase-B: b fastest (coalesced everywhere)
    const int pb_sl = tid >> 7;

    for (int t = 0; t < T_; t++) {
        // ---- Phase A: load h chunk (this CTA's 128 k-rows x 128 b, 64 KB, via L2)
        const float* hsrc = &g_h[dir * (H_ * B_) + kc * 128 * B_];
        for (int i = tid*4; i < 128*B_; i += REC_THREADS*4) {
            float4 v = __ldcg(reinterpret_cast<const float4*>(hsrc + i));
            *reinterpret_cast<float4*>(&hs[i]) = v;
        }
        __syncthreads();

        float acc[6][8];
        #pragma unroll
        for (int j = 0; j < 6; j++)
            #pragma unroll
            for (int i = 0; i < 8; i++) acc[j][i] = 0.f;

        #pragma unroll 4
        for (int k = 0; k < 128; k++) {
            float4 h0 = *reinterpret_cast<const float4*>(&hs[k*128 + b0]);
            float4 h1 = *reinterpret_cast<const float4*>(&hs[k*128 + b0 + 4]);
            float hf[8] = {h0.x,h0.y,h0.z,h0.w,h1.x,h1.y,h1.z,h1.w};
            #pragma unroll
            for (int j = 0; j < 6; j++) {
                float w = ws[k*96 + wg0 + j];
                #pragma unroll
                for (int i = 0; i < 8; i++)
                    acc[j][i] = fmaf(w, hf[i], acc[j][i]);
            }
        }

        // Write partials: P[g][kc][b]  (b contiguous -> STG.128, coalesced)
        #pragma unroll
        for (int j = 0; j < 6; j++) {
            int g = gg0 + wg0 + j;
            float* dst = &g_P[((size_t)g*4 + kc) * B_ + b0];
            __stcg(reinterpret_cast<float4*>(dst),
                   make_float4(acc[j][0], acc[j][1], acc[j][2], acc[j][3]));
            __stcg(reinterpret_cast<float4*>(dst + 4),
                   make_float4(acc[j][4], acc[j][5], acc[j][6], acc[j][7]));
        }
        __threadfence();
        grid_barrier();

        // ---- Phase B: gating. Each thread owns 4 (dir,j) combos for its b.
        #pragma unroll
        for (int it = 0; it < 4; it++) {
            int v  = cta*8 + pb_sl*4 + it;   // 0..1023 = dir*512 + j
            int d2 = v >> 9;
            int j  = v & 511;
            const float* bh = d2 ? bhb : bhf;
            int te = d2 ? (T_ - 1 - t) : t;  // backward dir reads reversed sequence
            int gb = d2 * G3;

            float hg[3], xg[3];
            #pragma unroll
            for (int gate = 0; gate < 3; gate++) {
                int g = gb + gate*H_ + j;
                float s = bh[gate*H_ + j];
                #pragma unroll
                for (int c = 0; c < 4; c++)
                    s += __ldcg(&g_P[((size_t)g*4 + c) * B_ + pb_b]);
                hg[gate] = s;
                xg[gate] = __ldcg(&g_xpT[((size_t)te * GT + g) * B_ + pb_b]);
            }
            float r = 1.f / (1.f + expf(-(xg[0] + hg[0])));
            float z = 1.f / (1.f + expf(-(xg[1] + hg[1])));
            float n = tanhf(xg[2] + r * hg[2]);
            float* hp = &g_h[(d2*H_ + j) * B_ + pb_b];
            float ho = __ldcg(hp);
            __stcg(hp, (1.f - z) * n + z * ho);
        }
        __threadfence();
        grid_barrier();
    }
}

// =================================================================================
// Phase 3: final FC + sigmoid.  out[b] = sigmoid(sum_j hcat[j][b]*fc_w[j] + fc_b)
// g_h linear layout [dir*512 + j][b] is exactly the concat order.
// =================================================================================
__global__ void fc_kernel(const float* __restrict__ fcw,
                          const float* __restrict__ fcb,
                          float* __restrict__ out)
{
    int b = threadIdx.x;   // 128 threads
    float s = 0.f;
    for (int j = 0; j < 2*H_; j++)
        s = fmaf(g_h[j*B_ + b], fcw[j], s);
    out[b] = 1.f / (1.f + expf(-(s + fcb[0])));
}

// =================================================================================
extern "C" void kernel_launch(void* const* d_in, const int* in_sizes, int n_in,
                              void* d_out, int out_size)
{
    const int*   inputs = (const int*)  d_in[0];
    const float* emb    = (const float*)d_in[1];
    const float* Wihf   = (const float*)d_in[2];
    const float* Whhf   = (const float*)d_in[3];
    const float* bihf   = (const float*)d_in[4];
    const float* bhhf   = (const float*)d_in[5];
    const float* Wihb   = (const float*)d_in[6];
    const float* Whhb   = (const float*)d_in[7];
    const float* bihb   = (const float*)d_in[8];
    const float* bhhb   = (const float*)d_in[9];
    const float* fcw    = (const float*)d_in[10];
    const float* fcb    = (const float*)d_in[11];
    float* out = (float*)d_out;

    const int rec_smem = (96*128 + 128*128) * (int)sizeof(float);  // 112 KB
    cudaFuncSetAttribute(rec_kernel,
                         cudaFuncAttributeMaxDynamicSharedMemorySize, rec_smem);

    proj_kernel<<<dim3(T_, GT/128), 256>>>(inputs, emb, Wihf, Wihb, bihf, bihb);
    rec_kernel<<<NCTA_REC, REC_THREADS, rec_smem>>>(Whhf, Whhb, bhhf, bhhb);
    fc_kernel<<<1, B_>>>(fcw, fcb, out);

    (void)in_sizes; (void)n_in; (void)out_size;
}